// round 15
// baseline (speedup 1.0000x reference)
#include <cuda_runtime.h>
#include <cuda_fp16.h>
#include <math.h>

#define NN 50000
#define FF 128

// ---------------- scratch (device globals; no allocation) ----------------
__device__ __half d_xt1h[NN * 64];               // [N][4][16] halfs: 0..14 msg, 15 = ak1
__device__ float d_aq1[NN * 4];
__device__ __align__(16) float d_agg1[NN * 16];  // 0..14 sums, 15 denom
__device__ __half d_xt2h[NN * 64];               // [N][4][16] halfs: 0..9 msg, 10 = ak2
__device__ float d_aq2[NN * 4];
__device__ __align__(16) float d_agg2[NN * 16];  // 0..9 sums, 10 denom
// padded weight layout: [ft][f][cg(16)][8], col = cg*5 + c (c<5), zero pad
__device__ __align__(16) float d_CW1p[4 * 32 * 128];
__device__ float d_CW2[15 * 48];    // cols 0..39 = W2, 40..43 = W2@q2, 44..47 = W2@k2
__device__ float d_stats[64];       // [0..14] S1_1, [16..30] S2_1, [32..41] S1_2, [48..57] S2_2
__device__ float d_c1, d_c2;

// ---------------- helpers ----------------
__device__ __forceinline__ void red4(float* p, float a, float b, float c, float d) {
    asm volatile("red.global.add.v4.f32 [%0], {%1,%2,%3,%4};"
                 :: "l"(p), "f"(a), "f"(b), "f"(c), "f"(d) : "memory");
}
__device__ __forceinline__ float2 h2f(unsigned u) {
    __half2 h = *reinterpret_cast<__half2*>(&u);
    return __half22float2(h);
}

// ---------------- fused init: zero + build1 + build2 ----------------
#define ZT (NN * 8 + 16)                    // float4 count to zero (agg1, agg2, stats)
#define B1N (4 * 32 * 128)
#define B2N (15 * 48)

__global__ void __launch_bounds__(256) k_init(
        const float* __restrict__ W1, const float* __restrict__ q1, const float* __restrict__ k1,
        const float* __restrict__ W2, const float* __restrict__ q2, const float* __restrict__ k2,
        const float* __restrict__ We1, const float* __restrict__ e1,
        const float* __restrict__ We2, const float* __restrict__ e2) {
    int i = blockIdx.x * 256 + threadIdx.x;
    if (i < ZT) {
        float4 z = make_float4(0.f, 0.f, 0.f, 0.f);
        if (i < NN * 4)                 reinterpret_cast<float4*>(d_agg1)[i] = z;
        else if (i < NN * 8)            reinterpret_cast<float4*>(d_agg2)[i - NN * 4] = z;
        else                            reinterpret_cast<float4*>(d_stats)[i - NN * 8] = z;
        return;
    }
    i -= ZT;
    if (i < B1N) {
        int c8 = i & 7, cg = (i >> 3) & 15, f = (i >> 7) & 31, ft = i >> 12;
        int fg = ft * 32 + f;
        float v = 0.f;
        int col = cg * 5 + c8;
        if (c8 < 5 && col < 68) {
            if (col < 60) {
                int r = col / 15, o = col % 15;
                v = W1[(r * 128 + fg) * 15 + o];
            } else if (col < 64) {
                int r = col - 60; float s = 0.f;
                for (int o = 0; o < 15; ++o) s += W1[(r * 128 + fg) * 15 + o] * q1[o];
                v = s;
            } else {
                int r = col - 64; float s = 0.f;
                for (int o = 0; o < 15; ++o) s += W1[(r * 128 + fg) * 15 + o] * k1[o];
                v = s;
            }
        }
        d_CW1p[i] = v;
        return;
    }
    i -= B1N;
    if (i == 0) {
        float s = 0.f;
        for (int o = 0; o < 15; ++o) s += We1[o] * e1[o];
        d_c1 = s;
        float t = 0.f;
        for (int o = 0; o < 10; ++o) t += We2[o] * e2[o];
        d_c2 = t;
    }
    if (i < B2N) {
        int f = i / 48, c = i % 48;
        float v;
        if (c < 40) {
            int r = c / 10, o = c % 10;
            v = W2[(r * 15 + f) * 10 + o];
        } else if (c < 44) {
            int r = c - 40; float s = 0.f;
            for (int o = 0; o < 10; ++o) s += W2[(r * 15 + f) * 10 + o] * q2[o];
            v = s;
        } else {
            int r = c - 44; float s = 0.f;
            for (int o = 0; o < 10; ++o) s += W2[(r * 15 + f) * 10 + o] * k2[o];
            v = s;
        }
        d_CW2[i] = v;
    }
}

// ---------------- layer-1 GEMM: [N,128] @ [128,68] ----------------
__global__ void __launch_bounds__(256) k_gemm1(const float* __restrict__ x, int n_nodes) {
    __shared__ __align__(16) float xs[64 * 36];
    __shared__ __align__(16) float ws[32 * 128];
    const int tid = threadIdx.x;
    const int nbase = blockIdx.x * 64;
    const int ng = tid >> 4, cg = tid & 15;
    const int n0 = ng * 4;

    float acc[4][5];
#pragma unroll
    for (int i = 0; i < 4; ++i)
#pragma unroll
        for (int c = 0; c < 5; ++c) acc[i][c] = 0.f;

    const bool full = (nbase + 64 <= n_nodes);

    for (int ft = 0; ft < 4; ++ft) {
#pragma unroll
        for (int k = 0; k < 2; ++k) {
            int idx = k * 256 + tid;
            int nl = idx >> 3, q = idx & 7;
            int n = nbase + nl;
            float4 v = make_float4(0.f, 0.f, 0.f, 0.f);
            if (full || n < n_nodes)
                v = *reinterpret_cast<const float4*>(x + (size_t)n * FF + ft * 32 + q * 4);
            *reinterpret_cast<float4*>(&xs[nl * 36 + q * 4]) = v;
        }
        {
            const float4* src = reinterpret_cast<const float4*>(d_CW1p + ft * 4096);
            float4* dst = reinterpret_cast<float4*>(ws);
#pragma unroll
            for (int k = 0; k < 4; ++k) dst[k * 256 + tid] = src[k * 256 + tid];
        }
        __syncthreads();

#pragma unroll
        for (int f = 0; f < 32; ++f) {
            const float* wr = &ws[f * 128 + cg * 8];
            float4 wa = *reinterpret_cast<const float4*>(wr);
            float w4 = wr[4];
            float x0 = xs[(n0 + 0) * 36 + f];
            float x1 = xs[(n0 + 1) * 36 + f];
            float x2 = xs[(n0 + 2) * 36 + f];
            float x3 = xs[(n0 + 3) * 36 + f];
#pragma unroll
            for (int i = 0; i < 4; ++i) {
                float xi = (i == 0) ? x0 : (i == 1) ? x1 : (i == 2) ? x2 : x3;
                acc[i][0] += xi * wa.x;
                acc[i][1] += xi * wa.y;
                acc[i][2] += xi * wa.z;
                acc[i][3] += xi * wa.w;
                acc[i][4] += xi * w4;
            }
        }
        __syncthreads();
    }

#pragma unroll
    for (int i = 0; i < 4; ++i) {
        int n = nbase + n0 + i;
        if (n >= n_nodes) break;
#pragma unroll
        for (int c = 0; c < 5; ++c) {
            int col = cg * 5 + c;
            if (col >= 68) break;
            float v = acc[i][c];
            if (col < 60)      d_xt1h[n * 64 + (col / 15) * 16 + (col % 15)] = __float2half_rn(v);
            else if (col < 64) d_aq1[n * 4 + col - 60] = v;
            else               d_xt1h[n * 64 + (col - 64) * 16 + 15] = __float2half_rn(v);
        }
    }
}

// ---------------- edge pass 1: 2 edges/thread, fp16 gathers ----------------
__global__ void __launch_bounds__(256) k_edge1(const int* __restrict__ ei, const int* __restrict__ et,
                                               const float* __restrict__ ea, int ne) {
    int t = blockIdx.x * 256 + threadIdx.x;
    int e0 = t * 2;
    if (e0 >= ne) return;
    bool two = (e0 + 1 < ne);
    int2 ss, rr; float2 aa;
    int dA, dB = 0;
    if (two) {
        ss = reinterpret_cast<const int2*>(ei)[t];
        rr = reinterpret_cast<const int2*>(et)[t];
        aa = reinterpret_cast<const float2*>(ea)[t];
        dA = ei[ne + e0]; dB = ei[ne + e0 + 1];
    } else {
        ss.x = ei[e0]; ss.y = ss.x;
        rr.x = et[e0]; rr.y = rr.x;
        aa.x = ea[e0]; aa.y = aa.x;
        dA = ei[ne + e0];
    }
    const uint4* xA = reinterpret_cast<const uint4*>(d_xt1h + ((size_t)ss.x * 4 + rr.x) * 16);
    uint4 a0 = xA[0], a1 = xA[1];
    float aqA = d_aq1[dA * 4 + rr.x];
    uint4 b0, b1; float aqB = 0.f;
    if (two) {
        const uint4* xB = reinterpret_cast<const uint4*>(d_xt1h + ((size_t)ss.y * 4 + rr.y) * 16);
        b0 = xB[0]; b1 = xB[1];
        aqB = d_aq1[dB * 4 + rr.y];
    }
    // edge A
    {
        float2 f0 = h2f(a0.x), f1 = h2f(a0.y), f2 = h2f(a0.z), f3 = h2f(a0.w);
        float2 f4 = h2f(a1.x), f5 = h2f(a1.y), f6 = h2f(a1.z), f7 = h2f(a1.w);
        float a = aqA + f7.y + aa.x * d_c1;
        a = (a > 0.f) ? a : 0.2f * a;
        float ex = __expf(a);
        float* ag = d_agg1 + (size_t)dA * 16;
        red4(ag + 0,  ex * f0.x, ex * f0.y, ex * f1.x, ex * f1.y);
        red4(ag + 4,  ex * f2.x, ex * f2.y, ex * f3.x, ex * f3.y);
        red4(ag + 8,  ex * f4.x, ex * f4.y, ex * f5.x, ex * f5.y);
        red4(ag + 12, ex * f6.x, ex * f6.y, ex * f7.x, ex);   // slot15 = denom
    }
    if (two) {
        float2 f0 = h2f(b0.x), f1 = h2f(b0.y), f2 = h2f(b0.z), f3 = h2f(b0.w);
        float2 f4 = h2f(b1.x), f5 = h2f(b1.y), f6 = h2f(b1.z), f7 = h2f(b1.w);
        float a = aqB + f7.y + aa.y * d_c1;
        a = (a > 0.f) ? a : 0.2f * a;
        float ex = __expf(a);
        float* ag = d_agg1 + (size_t)dB * 16;
        red4(ag + 0,  ex * f0.x, ex * f0.y, ex * f1.x, ex * f1.y);
        red4(ag + 4,  ex * f2.x, ex * f2.y, ex * f3.x, ex * f3.y);
        red4(ag + 8,  ex * f4.x, ex * f4.y, ex * f5.x, ex * f5.y);
        red4(ag + 12, ex * f6.x, ex * f6.y, ex * f7.x, ex);
    }
}

// ---------------- post1: BN stats on t = agg1*inv (lane-parallel scan) ----------------
__global__ void __launch_bounds__(256) k_post1(int n_nodes) {
    const int tot = n_nodes * 16;
    const int stride = gridDim.x * 256;          // multiple of 256
    int i = blockIdx.x * 256 + threadIdx.x;
    const int lane = threadIdx.x & 31;
    const int col = i & 15;                      // fixed per thread
    __shared__ float s1[16], s2[16];
    if (threadIdx.x < 16) { s1[threadIdx.x] = 0.f; s2[threadIdx.x] = 0.f; }
    __syncthreads();
    float a1 = 0.f, a2 = 0.f;
    for (; i < tot; i += stride) {
        float v = d_agg1[i];
        float denom = __shfl_sync(0xffffffffu, v, lane | 15);
        float tt = v / (denom + 1e-16f);
        if (col < 15) { a1 += tt; a2 += tt * tt; }
    }
    a1 += __shfl_down_sync(0xffffffffu, a1, 16);
    a2 += __shfl_down_sync(0xffffffffu, a2, 16);
    if (lane < 15) { atomicAdd(&s1[col], a1); atomicAdd(&s2[col], a2); }
    __syncthreads();
    if (threadIdx.x < 15) {
        atomicAdd(&d_stats[threadIdx.x], s1[threadIdx.x]);
        atomicAdd(&d_stats[16 + threadIdx.x], s2[threadIdx.x]);
    }
}

// ---------------- layer-2: inline BN finalize + BN+ELU + [N,15] @ [15,48] ----------------
__global__ void __launch_bounds__(256) k_gemm2(const float* __restrict__ b1,
                                               const float* __restrict__ g1, const float* __restrict__ bt1,
                                               int n_nodes) {
    __shared__ float w2s[720];
    __shared__ float bns[15], bnb[15];
    if (threadIdx.x < 15) {
        int o = threadIdx.x;
        float invn = 1.f / (float)n_nodes;
        float mt = d_stats[o] * invn;
        float var = d_stats[16 + o] * invn - mt * mt;
        float sc = g1[o] * rsqrtf(var + 1e-5f);
        bns[o] = sc;
        bnb[o] = bt1[o] - mt * sc;               // x = (t - mt)*sc*g + beta ; h=t+b1 folds out
    }
    for (int i = threadIdx.x; i < 720; i += 256) w2s[i] = d_CW2[i];
    __syncthreads();
    int n = blockIdx.x * 256 + threadIdx.x;
    if (n >= n_nodes) return;
    const float4* ag = reinterpret_cast<const float4*>(d_agg1 + (size_t)n * 16);
    float4 q0 = ag[0], q1 = ag[1], q2 = ag[2], q3 = ag[3];
    float inv = 1.f / (q3.w + 1e-16f);
    float tv[15] = {q0.x, q0.y, q0.z, q0.w, q1.x, q1.y, q1.z, q1.w,
                    q2.x, q2.y, q2.z, q2.w, q3.x, q3.y, q3.z};
    float x2[15];
#pragma unroll
    for (int o = 0; o < 15; ++o) {
        float v = tv[o] * inv * bns[o] + bnb[o];
        x2[o] = (v > 0.f) ? v : expm1f(v);
    }
    float outv[48];
#pragma unroll
    for (int c = 0; c < 48; ++c) {
        float s = 0.f;
#pragma unroll
        for (int i = 0; i < 15; ++i) s += x2[i] * w2s[i * 48 + c];
        outv[c] = s;
    }
#pragma unroll
    for (int c = 0; c < 40; ++c)
        d_xt2h[n * 64 + (c / 10) * 16 + (c % 10)] = __float2half_rn(outv[c]);
#pragma unroll
    for (int r = 0; r < 4; ++r) {
        d_aq2[n * 4 + r] = outv[40 + r];
        d_xt2h[n * 64 + r * 16 + 10] = __float2half_rn(outv[44 + r]);   // ak2
    }
}

// ---------------- edge pass 2: 2 edges/thread, fp16 gathers ----------------
__global__ void __launch_bounds__(256) k_edge2(const int* __restrict__ ei, const int* __restrict__ et,
                                               const float* __restrict__ ea, int ne) {
    int t = blockIdx.x * 256 + threadIdx.x;
    int e0 = t * 2;
    if (e0 >= ne) return;
    bool two = (e0 + 1 < ne);
    int2 ss, rr; float2 aa;
    int dA, dB = 0;
    if (two) {
        ss = reinterpret_cast<const int2*>(ei)[t];
        rr = reinterpret_cast<const int2*>(et)[t];
        aa = reinterpret_cast<const float2*>(ea)[t];
        dA = ei[ne + e0]; dB = ei[ne + e0 + 1];
    } else {
        ss.x = ei[e0]; ss.y = ss.x;
        rr.x = et[e0]; rr.y = rr.x;
        aa.x = ea[e0]; aa.y = aa.x;
        dA = ei[ne + e0];
    }
    const __half* pA = d_xt1h;  // dummy init to keep compiler happy (unused)
    (void)pA;
    const uint4* xA = reinterpret_cast<const uint4*>(d_xt2h + ((size_t)ss.x * 4 + rr.x) * 16);
    uint4 a0 = xA[0];
    uint2 a1 = *reinterpret_cast<const uint2*>(reinterpret_cast<const char*>(xA) + 16);
    float aqA = d_aq2[dA * 4 + rr.x];
    uint4 b0; uint2 b1; float aqB = 0.f;
    if (two) {
        const uint4* xB = reinterpret_cast<const uint4*>(d_xt2h + ((size_t)ss.y * 4 + rr.y) * 16);
        b0 = xB[0];
        b1 = *reinterpret_cast<const uint2*>(reinterpret_cast<const char*>(xB) + 16);
        aqB = d_aq2[dB * 4 + rr.y];
    }
    {
        float2 f0 = h2f(a0.x), f1 = h2f(a0.y), f2 = h2f(a0.z), f3 = h2f(a0.w);
        float2 f4 = h2f(a1.x), f5 = h2f(a1.y);   // f5.x = ak2
        float a = aqA + f5.x + aa.x * d_c2;
        a = (a > 0.f) ? a : 0.2f * a;
        float ex = __expf(a);
        float* ag = d_agg2 + (size_t)dA * 16;
        red4(ag + 0, ex * f0.x, ex * f0.y, ex * f1.x, ex * f1.y);
        red4(ag + 4, ex * f2.x, ex * f2.y, ex * f3.x, ex * f3.y);
        red4(ag + 8, ex * f4.x, ex * f4.y, ex, 0.f);          // slot10 = denom
    }
    if (two) {
        float2 f0 = h2f(b0.x), f1 = h2f(b0.y), f2 = h2f(b0.z), f3 = h2f(b0.w);
        float2 f4 = h2f(b1.x), f5 = h2f(b1.y);
        float a = aqB + f5.x + aa.y * d_c2;
        a = (a > 0.f) ? a : 0.2f * a;
        float ex = __expf(a);
        float* ag = d_agg2 + (size_t)dB * 16;
        red4(ag + 0, ex * f0.x, ex * f0.y, ex * f1.x, ex * f1.y);
        red4(ag + 4, ex * f2.x, ex * f2.y, ex * f3.x, ex * f3.y);
        red4(ag + 8, ex * f4.x, ex * f4.y, ex, 0.f);
    }
}

// ---------------- post2: BN stats on t = agg2*inv ----------------
__global__ void __launch_bounds__(256) k_post2(int n_nodes) {
    const int tot = n_nodes * 16;
    const int stride = gridDim.x * 256;
    int i = blockIdx.x * 256 + threadIdx.x;
    const int lane = threadIdx.x & 31;
    const int col = i & 15;
    __shared__ float s1[16], s2[16];
    if (threadIdx.x < 16) { s1[threadIdx.x] = 0.f; s2[threadIdx.x] = 0.f; }
    __syncthreads();
    float a1 = 0.f, a2 = 0.f;
    for (; i < tot; i += stride) {
        float v = d_agg2[i];
        float denom = __shfl_sync(0xffffffffu, v, (lane & 16) | 10);
        float tt = v / (denom + 1e-16f);
        if (col < 10) { a1 += tt; a2 += tt * tt; }
    }
    a1 += __shfl_down_sync(0xffffffffu, a1, 16);
    a2 += __shfl_down_sync(0xffffffffu, a2, 16);
    if (lane < 10) { atomicAdd(&s1[col], a1); atomicAdd(&s2[col], a2); }
    __syncthreads();
    if (threadIdx.x < 10) {
        atomicAdd(&d_stats[32 + threadIdx.x], s1[threadIdx.x]);
        atomicAdd(&d_stats[48 + threadIdx.x], s2[threadIdx.x]);
    }
}

// ---------------- head (inline BN2 finalize, reads agg2) ----------------
__global__ void __launch_bounds__(256) k_head(const float* __restrict__ b2,
                                              const float* __restrict__ g2, const float* __restrict__ bt2,
                                              const float* __restrict__ wh, const float* __restrict__ bh,
                                              float* __restrict__ out, int n_nodes) {
    __shared__ float bns[10], bnb[10];
    if (threadIdx.x < 10) {
        int o = threadIdx.x;
        float invn = 1.f / (float)n_nodes;
        float mt = d_stats[32 + o] * invn;
        float var = d_stats[48 + o] * invn - mt * mt;
        float sc = g2[o] * rsqrtf(var + 1e-5f);
        bns[o] = sc;
        bnb[o] = bt2[o] - mt * sc;
    }
    __syncthreads();
    int n = blockIdx.x * 256 + threadIdx.x;
    if (n >= n_nodes) return;
    const float4* ag = reinterpret_cast<const float4*>(d_agg2 + (size_t)n * 16);
    float4 q0 = ag[0], q1 = ag[1], q2 = ag[2];
    float inv = 1.f / (q2.z + 1e-16f);
    float tv[10] = {q0.x, q0.y, q0.z, q0.w, q1.x, q1.y, q1.z, q1.w, q2.x, q2.y};
    float s = bh[0];
#pragma unroll
    for (int o = 0; o < 10; ++o) {
        float v = tv[o] * inv * bns[o] + bnb[o];
        v = (v > 0.f) ? v : expm1f(v);
        s += v * wh[o];
    }
    out[n] = s;
}

// ---------------- launch ----------------
extern "C" void kernel_launch(void* const* d_in, const int* in_sizes, int n_in,
                              void* d_out, int out_size) {
    const float* x   = (const float*)d_in[0];
    const int*   ei  = (const int*)  d_in[1];
    const int*   et  = (const int*)  d_in[2];
    const float* ea  = (const float*)d_in[3];
    const float* W1  = (const float*)d_in[4];
    const float* q1  = (const float*)d_in[5];
    const float* k1  = (const float*)d_in[6];
    const float* e1  = (const float*)d_in[7];
    const float* We1 = (const float*)d_in[8];
    const float* b1  = (const float*)d_in[9];
    const float* W2  = (const float*)d_in[10];
    const float* q2  = (const float*)d_in[11];
    const float* k2  = (const float*)d_in[12];
    const float* e2  = (const float*)d_in[13];
    const float* We2 = (const float*)d_in[14];
    const float* b2  = (const float*)d_in[15];
    const float* g1  = (const float*)d_in[16];
    const float* bt1 = (const float*)d_in[17];
    const float* g2  = (const float*)d_in[18];
    const float* bt2 = (const float*)d_in[19];
    const float* wh  = (const float*)d_in[20];
    const float* bh  = (const float*)d_in[21];
    float* out = (float*)d_out;

    int n  = in_sizes[0] / FF;
    int ne = in_sizes[1] / 2;
    int npair = (ne + 1) / 2;

    int init_tot = ZT + B1N + B2N;
    k_init<<<(init_tot + 255) / 256, 256>>>(W1, q1, k1, W2, q2, k2, We1, e1, We2, e2);
    k_gemm1<<<(n + 63) / 64, 256>>>(x, n);
    k_edge1<<<(npair + 255) / 256, 256>>>(ei, et, ea, ne);
    k_post1<<<256, 256>>>(n);
    k_gemm2<<<(n + 255) / 256, 256>>>(b1, g1, bt1, n);
    k_edge2<<<(npair + 255) / 256, 256>>>(ei, et, ea, ne);
    k_post2<<<256, 256>>>(n);
    k_head<<<(n + 255) / 256, 256>>>(b2, g2, bt2, wh, bh, out, n);
}